// round 4
// baseline (speedup 1.0000x reference)
#include <cuda_runtime.h>
#include <math.h>

// Shapes are fixed by the dataset.
#define SB 2048
#define BB 2
#define HH 8
#define HD 128
#define DD 1024

// Scratch (static device globals: allowed; no runtime allocation).
__device__ float g_recip[(size_t)SB * SB];        // 16 MB: 1/(dist^2 + eps)
__device__ float g_masses[BB * HH * SB];          // (b,h,s)
__device__ float g_v[(size_t)BB * SB * DD];       // v = x @ v_w^T, (B,S,D)
__device__ float g_ho[(size_t)BB * SB * DD];      // head_out, (B,S,D)

// FMA-only exp for f in [0, 50]. Avoids MUFU throughput wall (67M exps).
__device__ __forceinline__ float fast_exp_pos(float f) {
    float t = f * 1.44269504088896340736f;
    float z = t + 12582912.0f;            // round-to-nearest int (n in [0,73])
    float n = z - 12582912.0f;
    float r = t - n;
    float p = 1.5403530e-4f;
    p = fmaf(p, r, 1.3333558e-3f);
    p = fmaf(p, r, 9.6181291e-3f);
    p = fmaf(p, r, 5.5504109e-2f);
    p = fmaf(p, r, 2.4022651e-1f);
    p = fmaf(p, r, 6.9314718e-1f);
    p = fmaf(p, r, 1.0f);
    int e = (int)n;
    return p * __int_as_float((e + 127) << 23);
}

// ---------------------------------------------------------------------------
// Kernel 1: recip[q,k] = 1 / (dist(q,k)^2 + 1e-6), warped distance.
// ---------------------------------------------------------------------------
__global__ void k_recip(const float* __restrict__ pos) {
    int idx = blockIdx.x * blockDim.x + threadIdx.x;   // S*S = 4M threads
    int q = idx >> 11;
    int k = idx & (SB - 1);
    float4 q0 = *(const float4*)(pos + q * 8);
    float4 q1 = *(const float4*)(pos + q * 8 + 4);
    float4 k0 = *(const float4*)(pos + k * 8);
    float4 k1 = *(const float4*)(pos + k * 8 + 4);
    float d2 = 1e-12f;
    float df;
    df = q0.x - k0.x; d2 = fmaf(df, df, d2);
    df = q0.y - k0.y; d2 = fmaf(df, df, d2);
    df = q0.z - k0.z; d2 = fmaf(df, df, d2);
    df = q0.w - k0.w; d2 = fmaf(df, df, d2);
    df = q1.x - k1.x; d2 = fmaf(df, df, d2);
    df = q1.y - k1.y; d2 = fmaf(df, df, d2);
    df = q1.z - k1.z; d2 = fmaf(df, df, d2);
    df = q1.w - k1.w; d2 = fmaf(df, df, d2);
    float dist = sqrtf(d2);
    dist = dist * (1.0f + 0.15f * __sinf(dist));   // |x| <= ~12, MUFU.SIN fine
    dist = fmaxf(dist, 0.0f);
    g_recip[idx] = __fdividef(1.0f, fmaf(dist, dist, 1e-6f));
}

// ---------------------------------------------------------------------------
// Kernel 2: masses[b,h,s] = sigmoid(dot(x[b,s,h*128:+128], mass_w[h])).
// ---------------------------------------------------------------------------
__global__ void k_masses(const float* __restrict__ x, const float* __restrict__ mw) {
    int g = blockIdx.x * 8 + (threadIdx.x >> 5);   // 0 .. B*H*S-1
    int lane = threadIdx.x & 31;
    int b = g >> 14;          // H*S = 16384
    int h = (g >> 11) & 7;
    int s = g & 2047;
    const float* xr = x + ((size_t)b * SB + s) * DD + h * HD;
    const float* wr = mw + h * HD;
    float sum = 0.f;
#pragma unroll
    for (int i = 0; i < 4; i++)
        sum = fmaf(xr[lane + 32 * i], wr[lane + 32 * i], sum);
#pragma unroll
    for (int o = 16; o; o >>= 1)
        sum += __shfl_xor_sync(0xffffffffu, sum, o);
    if (lane == 0)
        g_masses[g] = 1.0f / (1.0f + __expf(-sum));
}

// ---------------------------------------------------------------------------
// Kernels 3 & 5: C[m,n] = sum_k A[m,k] * Bw[n,k]  (NT GEMM, all row-major).
// M=4096, N=K=1024. 128x128 tile, 256 threads, 8x8 micro-tile.
// Reg-staged double buffer; 2 CTAs/SM for wave balance + latency hiding.
// ---------------------------------------------------------------------------
__global__ __launch_bounds__(256, 2) void k_gemm_nt(const float* __restrict__ Ain,
                                                    const float* __restrict__ Bw,
                                                    float* __restrict__ Cext,
                                                    int mode) {
    const float* A = (mode == 0) ? Ain : g_ho;
    float* C = (mode == 0) ? g_v : Cext;
    const int K = DD, N = DD;

    __shared__ float As[2][16 * 128];   // [buf][kk][m]
    __shared__ float Bs[2][16 * 128];   // [buf][kk][n]

    int tid = threadIdx.x;
    int tx = tid & 15, ty = tid >> 4;
    int mbase = blockIdx.y * 128, nbase = blockIdx.x * 128;

    // Per-thread load coords: 512 float4s per operand per tile, 2 per thread.
    int row0 = (tid * 2) >> 2, seg0 = (tid * 2) & 3;
    int row1 = (tid * 2 + 1) >> 2, seg1 = (tid * 2 + 1) & 3;
    const float* pa0 = A + (size_t)(mbase + row0) * K + seg0 * 4;
    const float* pa1 = A + (size_t)(mbase + row1) * K + seg1 * 4;
    const float* pb0 = Bw + (size_t)(nbase + row0) * K + seg0 * 4;
    const float* pb1 = Bw + (size_t)(nbase + row1) * K + seg1 * 4;

    float acc[8][8];
#pragma unroll
    for (int i = 0; i < 8; i++)
#pragma unroll
        for (int j = 0; j < 8; j++) acc[i][j] = 0.f;

    float4 av0, av1, bv0, bv1;

    // Prologue: tile 0 -> regs -> buf 0.
    av0 = *(const float4*)(pa0);
    av1 = *(const float4*)(pa1);
    bv0 = *(const float4*)(pb0);
    bv1 = *(const float4*)(pb1);
    {
        As[0][(seg0 * 4 + 0) * 128 + row0] = av0.x;
        As[0][(seg0 * 4 + 1) * 128 + row0] = av0.y;
        As[0][(seg0 * 4 + 2) * 128 + row0] = av0.z;
        As[0][(seg0 * 4 + 3) * 128 + row0] = av0.w;
        As[0][(seg1 * 4 + 0) * 128 + row1] = av1.x;
        As[0][(seg1 * 4 + 1) * 128 + row1] = av1.y;
        As[0][(seg1 * 4 + 2) * 128 + row1] = av1.z;
        As[0][(seg1 * 4 + 3) * 128 + row1] = av1.w;
        Bs[0][(seg0 * 4 + 0) * 128 + row0] = bv0.x;
        Bs[0][(seg0 * 4 + 1) * 128 + row0] = bv0.y;
        Bs[0][(seg0 * 4 + 2) * 128 + row0] = bv0.z;
        Bs[0][(seg0 * 4 + 3) * 128 + row0] = bv0.w;
        Bs[0][(seg1 * 4 + 0) * 128 + row1] = bv1.x;
        Bs[0][(seg1 * 4 + 1) * 128 + row1] = bv1.y;
        Bs[0][(seg1 * 4 + 2) * 128 + row1] = bv1.z;
        Bs[0][(seg1 * 4 + 3) * 128 + row1] = bv1.w;
    }
    __syncthreads();

    int buf = 0;
    for (int kb = 0; kb < K; kb += 16) {
        bool more = (kb + 16 < K);
        if (more) {                     // issue LDGs early; consume after compute
            av0 = *(const float4*)(pa0 + kb + 16);
            av1 = *(const float4*)(pa1 + kb + 16);
            bv0 = *(const float4*)(pb0 + kb + 16);
            bv1 = *(const float4*)(pb1 + kb + 16);
        }
#pragma unroll
        for (int kk = 0; kk < 16; kk++) {
            float4 a0 = *(float4*)&As[buf][kk * 128 + ty * 8];
            float4 a1 = *(float4*)&As[buf][kk * 128 + ty * 8 + 4];
            float4 b0 = *(float4*)&Bs[buf][kk * 128 + tx * 8];
            float4 b1 = *(float4*)&Bs[buf][kk * 128 + tx * 8 + 4];
            float a[8] = {a0.x, a0.y, a0.z, a0.w, a1.x, a1.y, a1.z, a1.w};
            float bb[8] = {b0.x, b0.y, b0.z, b0.w, b1.x, b1.y, b1.z, b1.w};
#pragma unroll
            for (int i = 0; i < 8; i++)
#pragma unroll
                for (int j = 0; j < 8; j++)
                    acc[i][j] = fmaf(a[i], bb[j], acc[i][j]);
        }
        if (more) {
            int nb = buf ^ 1;
            As[nb][(seg0 * 4 + 0) * 128 + row0] = av0.x;
            As[nb][(seg0 * 4 + 1) * 128 + row0] = av0.y;
            As[nb][(seg0 * 4 + 2) * 128 + row0] = av0.z;
            As[nb][(seg0 * 4 + 3) * 128 + row0] = av0.w;
            As[nb][(seg1 * 4 + 0) * 128 + row1] = av1.x;
            As[nb][(seg1 * 4 + 1) * 128 + row1] = av1.y;
            As[nb][(seg1 * 4 + 2) * 128 + row1] = av1.z;
            As[nb][(seg1 * 4 + 3) * 128 + row1] = av1.w;
            Bs[nb][(seg0 * 4 + 0) * 128 + row0] = bv0.x;
            Bs[nb][(seg0 * 4 + 1) * 128 + row0] = bv0.y;
            Bs[nb][(seg0 * 4 + 2) * 128 + row0] = bv0.z;
            Bs[nb][(seg0 * 4 + 3) * 128 + row0] = bv0.w;
            Bs[nb][(seg1 * 4 + 0) * 128 + row1] = bv1.x;
            Bs[nb][(seg1 * 4 + 1) * 128 + row1] = bv1.y;
            Bs[nb][(seg1 * 4 + 2) * 128 + row1] = bv1.z;
            Bs[nb][(seg1 * 4 + 3) * 128 + row1] = bv1.w;
        }
        __syncthreads();
        buf ^= 1;
    }

#pragma unroll
    for (int i = 0; i < 8; i++) {
        float* dst = C + (size_t)(mbase + ty * 8 + i) * N + nbase + tx * 8;
        float4 o0 = {acc[i][0], acc[i][1], acc[i][2], acc[i][3]};
        float4 o1 = {acc[i][4], acc[i][5], acc[i][6], acc[i][7]};
        *(float4*)dst = o0;
        *(float4*)(dst + 4) = o1;
    }
}

// ---------------------------------------------------------------------------
// Kernel 4: fused attention, software-pipelined, 2 CTAs/SM.
// P-stage re-tiled: thread = 4 q-rows x 4 k-cols -> LDG.128 recip loads,
// STS.128 P stores. PV loop: 8x8 micro-tile (q x hd).
// ---------------------------------------------------------------------------
#define PST 36    // p_s row stride (floats): 16B-aligned, conflict-free
__global__ __launch_bounds__(256, 2) void k_attn() {
    __shared__ float p_s[128 * PST];       // [q][kk], padded
    __shared__ float v_s[32 * 128];        // [kk][c]
    __shared__ float mq_s[128];
    __shared__ float den_s[128];

    int tid = threadIdx.x;
    int tx = tid & 15, ty = tid >> 4;
    int c4 = tid & 7;                 // k-col group (4 cols) for P stage
    int rg = tid >> 3;                // q-row group (4 rows), 0..31
    int bh = blockIdx.y;              // 0..15
    int b = bh >> 3, h = bh & 7;
    int qbase = blockIdx.x * 128;

    const float* mass = g_masses + (size_t)bh * SB;
    const float* vbase = g_v + (size_t)b * SB * DD + h * HD;
    const float* recbase = g_recip + (size_t)qbase * SB;

    if (tid < 128) mq_s[tid] = mass[qbase + tid];
    __syncthreads();

    float acc[8][8];
#pragma unroll
    for (int i = 0; i < 8; i++)
#pragma unroll
        for (int j = 0; j < 8; j++) acc[i][j] = 0.f;
    float dpart[4];
#pragma unroll
    for (int i = 0; i < 4; i++) dpart[i] = 0.f;

    // V-prefetch coords: 4 float4 per thread (tile is 32x128 = 1024 float4).
    int vk[4], vc[4];
#pragma unroll
    for (int r = 0; r < 4; r++) {
        int i4 = r * 256 + tid;
        vk[r] = i4 >> 5;
        vc[r] = i4 & 31;
    }

    float4 vreg[4];
    float4 rec4[4];
    float4 mk4;

    // Prologue: prefetch tile kb=0 into registers.
#pragma unroll
    for (int r = 0; r < 4; r++)
        vreg[r] = *(const float4*)(vbase + (size_t)vk[r] * DD + vc[r] * 4);
    mk4 = *(const float4*)(mass + c4 * 4);
#pragma unroll
    for (int i = 0; i < 4; i++)
        rec4[i] = *(const float4*)(recbase + (size_t)(rg * 4 + i) * SB + c4 * 4);

    for (int kb = 0; kb < SB; kb += 32) {
        // Stage regs -> smem (V tile + exp'd P tile).
#pragma unroll
        for (int r = 0; r < 4; r++)
            *(float4*)&v_s[vk[r] * 128 + vc[r] * 4] = vreg[r];
#pragma unroll
        for (int i = 0; i < 4; i++) {
            float mq = mq_s[rg * 4 + i];
            float e0 = fast_exp_pos(fminf(mq * mk4.x * rec4[i].x, 50.0f));
            float e1 = fast_exp_pos(fminf(mq * mk4.y * rec4[i].y, 50.0f));
            float e2 = fast_exp_pos(fminf(mq * mk4.z * rec4[i].z, 50.0f));
            float e3 = fast_exp_pos(fminf(mq * mk4.w * rec4[i].w, 50.0f));
            float4 pv = {e0, e1, e2, e3};
            *(float4*)&p_s[(rg * 4 + i) * PST + c4 * 4] = pv;
            dpart[i] += (e0 + e1) + (e2 + e3);
        }
        __syncthreads();

        // Prefetch next tile into regs; latency hidden by the PV loop below.
        if (kb + 32 < SB) {
            const float* vnext = vbase + (size_t)(kb + 32) * DD;
#pragma unroll
            for (int r = 0; r < 4; r++)
                vreg[r] = *(const float4*)(vnext + (size_t)vk[r] * DD + vc[r] * 4);
            mk4 = *(const float4*)(mass + kb + 32 + c4 * 4);
            const float* rnext = recbase + kb + 32;
#pragma unroll
            for (int i = 0; i < 4; i++)
                rec4[i] = *(const float4*)(rnext + (size_t)(rg * 4 + i) * SB + c4 * 4);
        }

        // PV: 32 kk x 8x8 FMAs.
#pragma unroll
        for (int kk = 0; kk < 32; kk++) {
            float a[8];
#pragma unroll
            for (int i = 0; i < 8; i++) a[i] = p_s[(ty * 8 + i) * PST + kk];
            float4 b0 = *(float4*)&v_s[kk * 128 + tx * 8];
            float4 b1 = *(float4*)&v_s[kk * 128 + tx * 8 + 4];
            float bb[8] = {b0.x, b0.y, b0.z, b0.w, b1.x, b1.y, b1.z, b1.w};
#pragma unroll
            for (int i = 0; i < 8; i++)
#pragma unroll
                for (int j = 0; j < 8; j++)
                    acc[i][j] = fmaf(a[i], bb[j], acc[i][j]);
        }
        __syncthreads();
    }

    // Row-sum reduce: row (rg*4+i) is covered by the 8 lanes sharing rg
    // (c4 = 0..7 = low 3 bits of lane id) -> butterfly over offsets 1,2,4.
#pragma unroll
    for (int i = 0; i < 4; i++) {
        float d = dpart[i];
        d += __shfl_xor_sync(0xffffffffu, d, 1);
        d += __shfl_xor_sync(0xffffffffu, d, 2);
        d += __shfl_xor_sync(0xffffffffu, d, 4);
        if (c4 == 0) den_s[rg * 4 + i] = d;
    }
    __syncthreads();

#pragma unroll
    for (int i = 0; i < 8; i++) {
        float inv = 1.0f / den_s[ty * 8 + i];
        float* dst = g_ho + ((size_t)b * SB + qbase + ty * 8 + i) * DD + h * HD + tx * 8;
        float4 o0 = {acc[i][0] * inv, acc[i][1] * inv, acc[i][2] * inv, acc[i][3] * inv};
        float4 o1 = {acc[i][4] * inv, acc[i][5] * inv, acc[i][6] * inv, acc[i][7] * inv};
        *(float4*)dst = o0;
        *(float4*)(dst + 4) = o1;
    }
}

// ---------------------------------------------------------------------------
extern "C" void kernel_launch(void* const* d_in, const int* in_sizes, int n_in,
                              void* d_out, int out_size) {
    const float* x      = (const float*)d_in[0];
    const float* mass_w = (const float*)d_in[1];
    const float* v_w    = (const float*)d_in[2];
    const float* out_w  = (const float*)d_in[3];
    const float* pos    = (const float*)d_in[4];
    float* out = (float*)d_out;

    k_recip<<<(SB * SB) / 256, 256>>>(pos);
    k_masses<<<(BB * HH * SB) / 8, 256>>>(x, mass_w);
    k_gemm_nt<<<dim3(DD / 128, (BB * SB) / 128), 256>>>(x, v_w, nullptr, 0);
    k_attn<<<dim3(SB / 128, BB * HH), 256>>>();
    k_gemm_nt<<<dim3(DD / 128, (BB * SB) / 128), 256>>>(nullptr, out_w, out, 1);
}

// round 6
// speedup vs baseline: 2.1908x; 2.1908x over previous
#include <cuda_runtime.h>
#include <cuda_bf16.h>
#include <cstdint>
#include <math.h>

// Shapes are fixed by the dataset.
#define SB 2048
#define BB 2
#define HH 8
#define HD 128
#define DD 1024

// Scratch (static device globals: allowed; no runtime allocation).
__device__ float g_recip[(size_t)SB * SB];        // 16 MB: 1/(dist^2 + eps)
__device__ float g_masses[BB * HH * SB];          // (b,h,s)
__device__ float g_v[(size_t)BB * SB * DD];       // v = x @ v_w^T, (B,S,D)
__device__ float g_ho[(size_t)BB * SB * DD];      // head_out, (B,S,D)
// Split-bf16 operands for tensor-core GEMMs.
__device__ __nv_bfloat16 g_xhi[(size_t)BB * SB * DD], g_xlo[(size_t)BB * SB * DD];
__device__ __nv_bfloat16 g_hohi[(size_t)BB * SB * DD], g_holo[(size_t)BB * SB * DD];
__device__ __nv_bfloat16 g_wvhi[(size_t)DD * DD], g_wvlo[(size_t)DD * DD];
__device__ __nv_bfloat16 g_wohi[(size_t)DD * DD], g_wolo[(size_t)DD * DD];

// ---------------- base-target tensor helpers (sm_80-era PTX) ---------------
__device__ __forceinline__ uint32_t smem_to_u32(const void* p) {
    uint32_t a;
    asm("{ .reg .u64 t; cvta.to.shared.u64 t, %1; cvt.u32.u64 %0, t; }"
        : "=r"(a) : "l"(p));
    return a;
}
__device__ __forceinline__ void cp16(uint32_t s, const void* g) {
    asm volatile("cp.async.cg.shared.global [%0], [%1], 16;" :: "r"(s), "l"(g));
}
#define CP_COMMIT() asm volatile("cp.async.commit_group;" ::: "memory")
#define CP_WAIT(n)  asm volatile("cp.async.wait_group %0;" :: "n"(n) : "memory")

__device__ __forceinline__ void ldsm_x4(uint32_t* r, uint32_t addr) {
    asm volatile("ldmatrix.sync.aligned.m8n8.x4.shared.b16 {%0,%1,%2,%3}, [%4];"
                 : "=r"(r[0]), "=r"(r[1]), "=r"(r[2]), "=r"(r[3]) : "r"(addr));
}
__device__ __forceinline__ void mma_bf16(float* d, const uint32_t* a,
                                         const uint32_t* b) {
    asm volatile(
        "mma.sync.aligned.m16n8k16.row.col.f32.bf16.bf16.f32 "
        "{%0,%1,%2,%3}, {%4,%5,%6,%7}, {%8,%9}, {%0,%1,%2,%3};"
        : "+f"(d[0]), "+f"(d[1]), "+f"(d[2]), "+f"(d[3])
        : "r"(a[0]), "r"(a[1]), "r"(a[2]), "r"(a[3]), "r"(b[0]), "r"(b[1]));
}

// FMA-only exp for f in [0, 50]. Avoids MUFU throughput wall (67M exps).
__device__ __forceinline__ float fast_exp_pos(float f) {
    float t = f * 1.44269504088896340736f;
    float z = t + 12582912.0f;            // round-to-nearest int
    float n = z - 12582912.0f;
    float r = t - n;
    float p = 1.5403530e-4f;
    p = fmaf(p, r, 1.3333558e-3f);
    p = fmaf(p, r, 9.6181291e-3f);
    p = fmaf(p, r, 5.5504109e-2f);
    p = fmaf(p, r, 2.4022651e-1f);
    p = fmaf(p, r, 6.9314718e-1f);
    p = fmaf(p, r, 1.0f);
    int e = (int)n;
    return p * __int_as_float((e + 127) << 23);
}

// ---------------------------------------------------------------------------
// Kernel 1: recip[q,k] = 1 / (dist(q,k)^2 + 1e-6), warped distance.
// ---------------------------------------------------------------------------
__global__ void k_recip(const float* __restrict__ pos) {
    int idx = blockIdx.x * blockDim.x + threadIdx.x;
    int q = idx >> 11;
    int k = idx & (SB - 1);
    float4 q0 = *(const float4*)(pos + q * 8);
    float4 q1 = *(const float4*)(pos + q * 8 + 4);
    float4 k0 = *(const float4*)(pos + k * 8);
    float4 k1 = *(const float4*)(pos + k * 8 + 4);
    float d2 = 1e-12f;
    float df;
    df = q0.x - k0.x; d2 = fmaf(df, df, d2);
    df = q0.y - k0.y; d2 = fmaf(df, df, d2);
    df = q0.z - k0.z; d2 = fmaf(df, df, d2);
    df = q0.w - k0.w; d2 = fmaf(df, df, d2);
    df = q1.x - k1.x; d2 = fmaf(df, df, d2);
    df = q1.y - k1.y; d2 = fmaf(df, df, d2);
    df = q1.z - k1.z; d2 = fmaf(df, df, d2);
    df = q1.w - k1.w; d2 = fmaf(df, df, d2);
    float dist = sqrtf(d2);
    dist = dist * (1.0f + 0.15f * __sinf(dist));
    dist = fmaxf(dist, 0.0f);
    g_recip[idx] = __fdividef(1.0f, fmaf(dist, dist, 1e-6f));
}

// ---------------------------------------------------------------------------
// Kernel 2: masses[b,h,s] = sigmoid(dot(x[b,s,h*128:+128], mass_w[h])).
// ---------------------------------------------------------------------------
__global__ void k_masses(const float* __restrict__ x, const float* __restrict__ mw) {
    int g = blockIdx.x * 8 + (threadIdx.x >> 5);
    int lane = threadIdx.x & 31;
    int b = g >> 14;
    int h = (g >> 11) & 7;
    int s = g & 2047;
    const float* xr = x + ((size_t)b * SB + s) * DD + h * HD;
    const float* wr = mw + h * HD;
    float sum = 0.f;
#pragma unroll
    for (int i = 0; i < 4; i++)
        sum = fmaf(xr[lane + 32 * i], wr[lane + 32 * i], sum);
#pragma unroll
    for (int o = 16; o; o >>= 1)
        sum += __shfl_xor_sync(0xffffffffu, sum, o);
    if (lane == 0)
        g_masses[g] = 1.0f / (1.0f + __expf(-sum));
}

// ---------------------------------------------------------------------------
// k_split: fp32 -> (bf16 hi, bf16 lo); hi = rn(x), lo = rn(x - hi).
// ---------------------------------------------------------------------------
__global__ void k_split(const float* __restrict__ src,
                        __nv_bfloat16* __restrict__ hi,
                        __nv_bfloat16* __restrict__ lo) {
    int i = (blockIdx.x * blockDim.x + threadIdx.x) * 4;
    float4 v = *(const float4*)(src + i);
    __nv_bfloat16 h0 = __float2bfloat16(v.x);
    __nv_bfloat16 h1 = __float2bfloat16(v.y);
    __nv_bfloat16 h2 = __float2bfloat16(v.z);
    __nv_bfloat16 h3 = __float2bfloat16(v.w);
    __nv_bfloat16 l0 = __float2bfloat16(v.x - __bfloat162float(h0));
    __nv_bfloat16 l1 = __float2bfloat16(v.y - __bfloat162float(h1));
    __nv_bfloat16 l2 = __float2bfloat16(v.z - __bfloat162float(h2));
    __nv_bfloat16 l3 = __float2bfloat16(v.w - __bfloat162float(h3));
    *(__nv_bfloat162*)(hi + i) = __nv_bfloat162(h0, h1);
    *(__nv_bfloat162*)(hi + i + 2) = __nv_bfloat162(h2, h3);
    *(__nv_bfloat162*)(lo + i) = __nv_bfloat162(l0, l1);
    *(__nv_bfloat162*)(lo + i + 2) = __nv_bfloat162(l2, l3);
}

// ---------------------------------------------------------------------------
// Tensor-core split-bf16 NT GEMM via mma.sync (base-target HMMA path).
// C[m,n] = sum_k A[m,k]*B[n,k]; A=Ahi+Alo, B=Bhi+Blo; D = AhiBhi+AhiBlo+AloBhi.
// CTA tile 128x128, Kc=64; 8 warps of 32(m)x64(n); m16n8k16 atoms.
// cp.async double-buffered smem; padded bf16 row stride 72 (conflict-free).
// ---------------------------------------------------------------------------
#define AST 72                       // padded bf16 stride
#define TILE_B (128 * AST * 2)       // 18432 bytes per tile
#define OFF_AH 0
#define OFF_AL TILE_B
#define OFF_BH (2 * TILE_B)
#define OFF_BL (3 * TILE_B)
#define STAGE_B (4 * TILE_B)         // 73728 bytes per stage
#define GT_SMEM (2 * STAGE_B)        // 147456

__global__ __launch_bounds__(256)
void k_gemm_tc(const __nv_bfloat16* __restrict__ Ah,
               const __nv_bfloat16* __restrict__ Al,
               const __nv_bfloat16* __restrict__ Bh,
               const __nv_bfloat16* __restrict__ Bl,
               float* __restrict__ C) {
    extern __shared__ char smem[];
    uint32_t sb = smem_to_u32(smem);
    int tid = threadIdx.x;
    int wid = tid >> 5, lane = tid & 31;
    int wm = wid & 3, wn = wid >> 2;             // warp tile: 32m x 64n
    int mbase = blockIdx.y * 128, nbase = blockIdx.x * 128;

    // Per-thread staging coords: each tile = 1024 uint4, 4 per thread.
    int lrow[4], lseg[4];
#pragma unroll
    for (int j = 0; j < 4; j++) {
        int i = j * 256 + tid;
        lrow[j] = i >> 3;
        lseg[j] = i & 7;
    }

    // ldmatrix lane-address components.
    int aoff = (wm * 32 + (lane & 15)) * (AST * 2) + (((lane >> 4) << 3) << 1);
    int boff = (wn * 64 + (lane & 7) + ((lane & 16) >> 1)) * (AST * 2) +
               ((lane & 8) << 1);

    float acc[2][8][4];
#pragma unroll
    for (int im = 0; im < 2; im++)
#pragma unroll
        for (int in = 0; in < 8; in++)
#pragma unroll
            for (int q = 0; q < 4; q++) acc[im][in][q] = 0.f;

    // --- stage loader ---
    auto load_chunk = [&](int c, int stage) {
        uint32_t s0 = sb + stage * STAGE_B;
        int kof = c * 64;
#pragma unroll
        for (int j = 0; j < 4; j++) {
            uint32_t so = (uint32_t)(lrow[j] * (AST * 2) + lseg[j] * 16);
            size_t ga = (size_t)(mbase + lrow[j]) * DD + kof + lseg[j] * 8;
            size_t gb = (size_t)(nbase + lrow[j]) * DD + kof + lseg[j] * 8;
            cp16(s0 + OFF_AH + so, Ah + ga);
            cp16(s0 + OFF_AL + so, Al + ga);
            cp16(s0 + OFF_BH + so, Bh + gb);
            cp16(s0 + OFF_BL + so, Bl + gb);
        }
    };

    load_chunk(0, 0);
    CP_COMMIT();

    for (int c = 0; c < 16; c++) {
        int cur = c & 1;
        if (c + 1 < 16) {
            load_chunk(c + 1, cur ^ 1);
            CP_COMMIT();
            CP_WAIT(1);
        } else {
            CP_WAIT(0);
        }
        __syncthreads();

        uint32_t base = sb + cur * STAGE_B;
#pragma unroll
        for (int ks = 0; ks < 4; ks++) {
            int k2 = ks * 32;                     // k0 * 2 bytes
            uint32_t aH[2][4], aL[2][4], bH[16], bL[16];
#pragma unroll
            for (int im = 0; im < 2; im++) {
                ldsm_x4(aH[im], base + OFF_AH + aoff + im * 16 * (AST * 2) + k2);
                ldsm_x4(aL[im], base + OFF_AL + aoff + im * 16 * (AST * 2) + k2);
            }
#pragma unroll
            for (int g = 0; g < 4; g++) {
                ldsm_x4(bH + g * 4, base + OFF_BH + boff + g * 16 * (AST * 2) + k2);
                ldsm_x4(bL + g * 4, base + OFF_BL + boff + g * 16 * (AST * 2) + k2);
            }
#pragma unroll
            for (int im = 0; im < 2; im++)
#pragma unroll
                for (int in = 0; in < 8; in++) {
                    const uint32_t* bh = &bH[(in >> 1) * 4 + (in & 1) * 2];
                    const uint32_t* bl = &bL[(in >> 1) * 4 + (in & 1) * 2];
                    mma_bf16(acc[im][in], aH[im], bh);
                    mma_bf16(acc[im][in], aH[im], bl);
                    mma_bf16(acc[im][in], aL[im], bh);
                }
        }
        __syncthreads();
    }

    // Epilogue: m16n8 acc layout -> fp32 C (float2 stores).
#pragma unroll
    for (int im = 0; im < 2; im++)
#pragma unroll
        for (int in = 0; in < 8; in++) {
            int r0 = mbase + wm * 32 + im * 16 + (lane >> 2);
            int cc = nbase + wn * 64 + in * 8 + 2 * (lane & 3);
            float2 lo = {acc[im][in][0], acc[im][in][1]};
            float2 hi = {acc[im][in][2], acc[im][in][3]};
            *(float2*)(C + (size_t)r0 * DD + cc) = lo;
            *(float2*)(C + (size_t)(r0 + 8) * DD + cc) = hi;
        }
}

// ---------------------------------------------------------------------------
// Kernel 4: fused attention (R3-proven version), software-pipelined.
// ---------------------------------------------------------------------------
#define PSTRIDE 33
__global__ __launch_bounds__(256) void k_attn() {
    __shared__ float p_s[128 * PSTRIDE];   // [q][kk], padded
    __shared__ float v_s[32 * 128];        // [kk][c]
    __shared__ float mq_s[128];
    __shared__ float den_s[128];

    int tid = threadIdx.x;
    int tx = tid & 15, ty = tid >> 4;
    int w = tid >> 5, lane = tid & 31;
    int bh = blockIdx.y;              // 0..15
    int b = bh >> 3, h = bh & 7;
    int qbase = blockIdx.x * 128;

    const float* mass = g_masses + (size_t)bh * SB;
    const float* vbase = g_v + (size_t)b * SB * DD + h * HD;
    const float* recbase = g_recip + (size_t)qbase * SB;

    if (tid < 128) mq_s[tid] = mass[qbase + tid];
    __syncthreads();

    float acc[8][8];
#pragma unroll
    for (int i = 0; i < 8; i++)
#pragma unroll
        for (int j = 0; j < 8; j++) acc[i][j] = 0.f;
    float dpart[16];
#pragma unroll
    for (int r = 0; r < 16; r++) dpart[r] = 0.f;

    int vk[4], vc[4];
#pragma unroll
    for (int r = 0; r < 4; r++) {
        int i4 = r * 256 + tid;
        vk[r] = i4 >> 5;
        vc[r] = i4 & 31;
    }
    int kkc = tid & 31;
    int qrow = tid >> 5;

    float4 vreg[4];
    float rec[16];
    float mk;

#pragma unroll
    for (int r = 0; r < 4; r++)
        vreg[r] = *(const float4*)(vbase + (size_t)vk[r] * DD + vc[r] * 4);
    mk = __ldg(mass + kkc);
#pragma unroll
    for (int r = 0; r < 16; r++)
        rec[r] = recbase[(size_t)(r * 8 + qrow) * SB + kkc];

    for (int kb = 0; kb < SB; kb += 32) {
#pragma unroll
        for (int r = 0; r < 4; r++)
            *(float4*)&v_s[vk[r] * 128 + vc[r] * 4] = vreg[r];
        float mqv;
#pragma unroll
        for (int r = 0; r < 16; r++) {
            int qq = r * 8 + qrow;
            mqv = mq_s[qq];
            float f = fminf(mqv * mk * rec[r], 50.0f);
            float ev = fast_exp_pos(f);
            p_s[qq * PSTRIDE + kkc] = ev;
            dpart[r] += ev;
        }
        __syncthreads();

        if (kb + 32 < SB) {
            const float* vnext = vbase + (size_t)(kb + 32) * DD;
#pragma unroll
            for (int r = 0; r < 4; r++)
                vreg[r] = *(const float4*)(vnext + (size_t)vk[r] * DD + vc[r] * 4);
            mk = __ldg(mass + kb + 32 + kkc);
            const float* rnext = recbase + kb + 32;
#pragma unroll
            for (int r = 0; r < 16; r++)
                rec[r] = rnext[(size_t)(r * 8 + qrow) * SB + kkc];
        }

#pragma unroll
        for (int kk = 0; kk < 32; kk++) {
            float a[8];
#pragma unroll
            for (int i = 0; i < 8; i++) a[i] = p_s[(ty * 8 + i) * PSTRIDE + kk];
            float4 b0 = *(float4*)&v_s[kk * 128 + tx * 8];
            float4 b1 = *(float4*)&v_s[kk * 128 + tx * 8 + 4];
            float bb[8] = {b0.x, b0.y, b0.z, b0.w, b1.x, b1.y, b1.z, b1.w};
#pragma unroll
            for (int i = 0; i < 8; i++)
#pragma unroll
                for (int j = 0; j < 8; j++)
                    acc[i][j] = fmaf(a[i], bb[j], acc[i][j]);
        }
        __syncthreads();
    }

#pragma unroll
    for (int r = 0; r < 16; r++) {
        float d = dpart[r];
#pragma unroll
        for (int o = 16; o; o >>= 1) d += __shfl_xor_sync(0xffffffffu, d, o);
        if (lane == 0) den_s[r * 8 + w] = d;
    }
    __syncthreads();

#pragma unroll
    for (int i = 0; i < 8; i++) {
        float inv = 1.0f / den_s[ty * 8 + i];
        float* dst = g_ho + ((size_t)b * SB + qbase + ty * 8 + i) * DD + h * HD + tx * 8;
        float4 o0 = {acc[i][0] * inv, acc[i][1] * inv, acc[i][2] * inv, acc[i][3] * inv};
        float4 o1 = {acc[i][4] * inv, acc[i][5] * inv, acc[i][6] * inv, acc[i][7] * inv};
        *(float4*)dst = o0;
        *(float4*)(dst + 4) = o1;
    }
}

// ---------------------------------------------------------------------------
extern "C" void kernel_launch(void* const* d_in, const int* in_sizes, int n_in,
                              void* d_out, int out_size) {
    const float* x      = (const float*)d_in[0];
    const float* mass_w = (const float*)d_in[1];
    const float* v_w    = (const float*)d_in[2];
    const float* out_w  = (const float*)d_in[3];
    const float* pos    = (const float*)d_in[4];
    float* out = (float*)d_out;

    cudaFuncSetAttribute(k_gemm_tc, cudaFuncAttributeMaxDynamicSharedMemorySize,
                         GT_SMEM);

    __nv_bfloat16 *xhi, *xlo, *hohi, *holo, *wvhi, *wvlo, *wohi, *wolo;
    float *vptr, *hoptr;
    cudaGetSymbolAddress((void**)&xhi, g_xhi);
    cudaGetSymbolAddress((void**)&xlo, g_xlo);
    cudaGetSymbolAddress((void**)&hohi, g_hohi);
    cudaGetSymbolAddress((void**)&holo, g_holo);
    cudaGetSymbolAddress((void**)&wvhi, g_wvhi);
    cudaGetSymbolAddress((void**)&wvlo, g_wvlo);
    cudaGetSymbolAddress((void**)&wohi, g_wohi);
    cudaGetSymbolAddress((void**)&wolo, g_wolo);
    cudaGetSymbolAddress((void**)&vptr, g_v);
    cudaGetSymbolAddress((void**)&hoptr, g_ho);

    const int NX = BB * SB * DD;      // 4.2M
    const int NW = DD * DD;           // 1M

    k_recip<<<(SB * SB) / 256, 256>>>(pos);
    k_masses<<<(BB * HH * SB) / 8, 256>>>(x, mass_w);
    k_split<<<NX / 1024, 256>>>(x, xhi, xlo);
    k_split<<<NW / 1024, 256>>>(v_w, wvhi, wvlo);
    k_split<<<NW / 1024, 256>>>(out_w, wohi, wolo);
    k_gemm_tc<<<dim3(DD / 128, (BB * SB) / 128), 256, GT_SMEM>>>(
        xhi, xlo, wvhi, wvlo, vptr);
    k_attn<<<dim3(SB / 128, BB * HH), 256>>>();
    k_split<<<NX / 1024, 256>>>(hoptr, hohi, holo);
    k_gemm_tc<<<dim3(DD / 128, (BB * SB) / 128), 256, GT_SMEM>>>(
        hohi, holo, wohi, wolo, out);
}

// round 8
// speedup vs baseline: 3.7290x; 1.7022x over previous
#include <cuda_runtime.h>
#include <cuda_bf16.h>
#include <cstdint>
#include <math.h>

#define SB 2048
#define BB 2
#define HH 8
#define HD 128
#define DD 1024

__device__ float g_recip[(size_t)SB * SB];
__device__ float g_masses[BB * HH * SB];
__device__ __nv_bfloat16 g_xhi[(size_t)BB * SB * DD], g_xlo[(size_t)BB * SB * DD];
__device__ __nv_bfloat16 g_vhi[(size_t)BB * SB * DD], g_vlo[(size_t)BB * SB * DD];
__device__ __nv_bfloat16 g_hohi[(size_t)BB * SB * DD], g_holo[(size_t)BB * SB * DD];
__device__ __nv_bfloat16 g_wvhi[(size_t)DD * DD], g_wvlo[(size_t)DD * DD];
__device__ __nv_bfloat16 g_wohi[(size_t)DD * DD], g_wolo[(size_t)DD * DD];

__device__ __forceinline__ uint32_t smem_to_u32(const void* p) {
    uint32_t a;
    asm("{ .reg .u64 t; cvta.to.shared.u64 t, %1; cvt.u32.u64 %0, t; }"
        : "=r"(a) : "l"(p));
    return a;
}
__device__ __forceinline__ void cp16(uint32_t s, const void* g) {
    asm volatile("cp.async.cg.shared.global [%0], [%1], 16;" :: "r"(s), "l"(g));
}
#define CP_COMMIT() asm volatile("cp.async.commit_group;" ::: "memory")
#define CP_WAIT(n)  asm volatile("cp.async.wait_group %0;" :: "n"(n) : "memory")

__device__ __forceinline__ void ldsm_x4(uint32_t* r, uint32_t addr) {
    asm volatile("ldmatrix.sync.aligned.m8n8.x4.shared.b16 {%0,%1,%2,%3}, [%4];"
                 : "=r"(r[0]), "=r"(r[1]), "=r"(r[2]), "=r"(r[3]) : "r"(addr));
}
__device__ __forceinline__ void ldsm_t_x4(uint32_t* r, uint32_t addr) {
    asm volatile("ldmatrix.sync.aligned.m8n8.x4.trans.shared.b16 {%0,%1,%2,%3}, [%4];"
                 : "=r"(r[0]), "=r"(r[1]), "=r"(r[2]), "=r"(r[3]) : "r"(addr));
}
__device__ __forceinline__ void mma_bf16(float* d, const uint32_t* a,
                                         const uint32_t* b) {
    asm volatile(
        "mma.sync.aligned.m16n8k16.row.col.f32.bf16.bf16.f32 "
        "{%0,%1,%2,%3}, {%4,%5,%6,%7}, {%8,%9}, {%0,%1,%2,%3};"
        : "+f"(d[0]), "+f"(d[1]), "+f"(d[2]), "+f"(d[3])
        : "r"(a[0]), "r"(a[1]), "r"(a[2]), "r"(a[3]), "r"(b[0]), "r"(b[1]));
}
__device__ __forceinline__ void split_bf(float v, __nv_bfloat16& h, __nv_bfloat16& l) {
    h = __float2bfloat16(v);
    l = __float2bfloat16(v - __bfloat162float(h));
}
__device__ __forceinline__ uint32_t pack_bf2_u(__nv_bfloat16 a, __nv_bfloat16 b) {
    __nv_bfloat162 t(a, b);
    return *(uint32_t*)&t;
}

__device__ __forceinline__ float fast_exp_pos(float f) {
    float t = f * 1.44269504088896340736f;
    float z = t + 12582912.0f;
    float n = z - 12582912.0f;
    float r = t - n;
    float p = 1.5403530e-4f;
    p = fmaf(p, r, 1.3333558e-3f);
    p = fmaf(p, r, 9.6181291e-3f);
    p = fmaf(p, r, 5.5504109e-2f);
    p = fmaf(p, r, 2.4022651e-1f);
    p = fmaf(p, r, 6.9314718e-1f);
    p = fmaf(p, r, 1.0f);
    int e = (int)n;
    return p * __int_as_float((e + 127) << 23);
}

__global__ void k_recip(const float* __restrict__ pos) {
    int idx = blockIdx.x * blockDim.x + threadIdx.x;
    int q = idx >> 11;
    int k = idx & (SB - 1);
    float4 q0 = *(const float4*)(pos + q * 8);
    float4 q1 = *(const float4*)(pos + q * 8 + 4);
    float4 k0 = *(const float4*)(pos + k * 8);
    float4 k1 = *(const float4*)(pos + k * 8 + 4);
    float d2 = 1e-12f;
    float df;
    df = q0.x - k0.x; d2 = fmaf(df, df, d2);
    df = q0.y - k0.y; d2 = fmaf(df, df, d2);
    df = q0.z - k0.z; d2 = fmaf(df, df, d2);
    df = q0.w - k0.w; d2 = fmaf(df, df, d2);
    df = q1.x - k1.x; d2 = fmaf(df, df, d2);
    df = q1.y - k1.y; d2 = fmaf(df, df, d2);
    df = q1.z - k1.z; d2 = fmaf(df, df, d2);
    df = q1.w - k1.w; d2 = fmaf(df, df, d2);
    float dist = sqrtf(d2);
    dist = dist * (1.0f + 0.15f * __sinf(dist));
    dist = fmaxf(dist, 0.0f);
    g_recip[idx] = __fdividef(1.0f, fmaf(dist, dist, 1e-6f));
}

__global__ void k_masses(const float* __restrict__ x, const float* __restrict__ mw) {
    int g = blockIdx.x * 8 + (threadIdx.x >> 5);
    int lane = threadIdx.x & 31;
    int b = g >> 14;
    int h = (g >> 11) & 7;
    int s = g & 2047;
    const float* xr = x + ((size_t)b * SB + s) * DD + h * HD;
    const float* wr = mw + h * HD;
    float sum = 0.f;
#pragma unroll
    for (int i = 0; i < 4; i++)
        sum = fmaf(xr[lane + 32 * i], wr[lane + 32 * i], sum);
#pragma unroll
    for (int o = 16; o; o >>= 1)
        sum += __shfl_xor_sync(0xffffffffu, sum, o);
    if (lane == 0)
        g_masses[g] = 1.0f / (1.0f + __expf(-sum));
}

__global__ void k_split(const float* __restrict__ src,
                        __nv_bfloat16* __restrict__ hi,
                        __nv_bfloat16* __restrict__ lo) {
    int i = (blockIdx.x * blockDim.x + threadIdx.x) * 4;
    float4 v = *(const float4*)(src + i);
    __nv_bfloat16 h0, h1, h2, h3, l0, l1, l2, l3;
    split_bf(v.x, h0, l0);
    split_bf(v.y, h1, l1);
    split_bf(v.z, h2, l2);
    split_bf(v.w, h3, l3);
    *(__nv_bfloat162*)(hi + i) = __nv_bfloat162(h0, h1);
    *(__nv_bfloat162*)(hi + i + 2) = __nv_bfloat162(h2, h3);
    *(__nv_bfloat162*)(lo + i) = __nv_bfloat162(l0, l1);
    *(__nv_bfloat162*)(lo + i + 2) = __nv_bfloat162(l2, l3);
}

#define AST 72
#define TILE_B (128 * AST * 2)
#define OFF_AH 0
#define OFF_AL TILE_B
#define OFF_BH (2 * TILE_B)
#define OFF_BL (3 * TILE_B)
#define STAGE_B (4 * TILE_B)
#define GT_SMEM (2 * STAGE_B)

__global__ __launch_bounds__(256)
void k_gemm_tc(const __nv_bfloat16* __restrict__ Ah,
               const __nv_bfloat16* __restrict__ Al,
               const __nv_bfloat16* __restrict__ Bh,
               const __nv_bfloat16* __restrict__ Bl,
               float* __restrict__ Cf,
               __nv_bfloat16* __restrict__ Chi,
               __nv_bfloat16* __restrict__ Clo) {
    extern __shared__ char smem[];
    uint32_t sb = smem_to_u32(smem);
    int tid = threadIdx.x;
    int wid = tid >> 5, lane = tid & 31;
    int wm = wid & 3, wn = wid >> 2;
    int mbase = blockIdx.y * 128, nbase = blockIdx.x * 128;

    int lrow[4], lseg[4];
#pragma unroll
    for (int j = 0; j < 4; j++) {
        int i = j * 256 + tid;
        lrow[j] = i >> 3;
        lseg[j] = i & 7;
    }
    int aoff = (wm * 32 + (lane & 15)) * (AST * 2) + (lane >> 4) * 16;
    int boff = (wn * 64 + (lane & 7) + ((lane & 16) >> 1)) * (AST * 2) +
               ((lane & 8) << 1);

    float acc[2][8][4];
#pragma unroll
    for (int im = 0; im < 2; im++)
#pragma unroll
        for (int in = 0; in < 8; in++)
#pragma unroll
            for (int q = 0; q < 4; q++) acc[im][in][q] = 0.f;

    auto load_chunk = [&](int c, int stage) {
        uint32_t s0 = sb + stage * STAGE_B;
        int kof = c * 64;
#pragma unroll
        for (int j = 0; j < 4; j++) {
            uint32_t so = (uint32_t)(lrow[j] * (AST * 2) + lseg[j] * 16);
            size_t ga = (size_t)(mbase + lrow[j]) * DD + kof + lseg[j] * 8;
            size_t gb = (size_t)(nbase + lrow[j]) * DD + kof + lseg[j] * 8;
            cp16(s0 + OFF_AH + so, Ah + ga);
            cp16(s0 + OFF_AL + so, Al + ga);
            cp16(s0 + OFF_BH + so, Bh + gb);
            cp16(s0 + OFF_BL + so, Bl + gb);
        }
    };

    load_chunk(0, 0);
    CP_COMMIT();

    for (int c = 0; c < 16; c++) {
        int cur = c & 1;
        if (c + 1 < 16) {
            load_chunk(c + 1, cur ^ 1);
            CP_COMMIT();
            CP_WAIT(1);
        } else {
            CP_WAIT(0);
        }
        __syncthreads();

        uint32_t base = sb + cur * STAGE_B;
#pragma unroll
        for (int ks = 0; ks < 4; ks++) {
            int k2 = ks * 32;
            uint32_t aH[2][4], aL[2][4], bH[16], bL[16];
#pragma unroll
            for (int im = 0; im < 2; im++) {
                ldsm_x4(aH[im], base + OFF_AH + aoff + im * 16 * (AST * 2) + k2);
                ldsm_x4(aL[im], base + OFF_AL + aoff + im * 16 * (AST * 2) + k2);
            }
#pragma unroll
            for (int g = 0; g < 4; g++) {
                ldsm_x4(bH + g * 4, base + OFF_BH + boff + g * 16 * (AST * 2) + k2);
                ldsm_x4(bL + g * 4, base + OFF_BL + boff + g * 16 * (AST * 2) + k2);
            }
#pragma unroll
            for (int im = 0; im < 2; im++)
#pragma unroll
                for (int in = 0; in < 8; in++) {
                    const uint32_t* bh = &bH[(in >> 1) * 4 + (in & 1) * 2];
                    const uint32_t* bl = &bL[(in >> 1) * 4 + (in & 1) * 2];
                    mma_bf16(acc[im][in], aH[im], bh);
                    mma_bf16(acc[im][in], aH[im], bl);
                    mma_bf16(acc[im][in], aL[im], bh);
                }
        }
        __syncthreads();
    }

#pragma unroll
    for (int im = 0; im < 2; im++)
#pragma unroll
        for (int in = 0; in < 8; in++) {
            int r0 = mbase + wm * 32 + im * 16 + (lane >> 2);
            int cc = nbase + wn * 64 + in * 8 + 2 * (lane & 3);
            if (Chi) {
                __nv_bfloat16 h0, h1, l0, l1;
                split_bf(acc[im][in][0], h0, l0);
                split_bf(acc[im][in][1], h1, l1);
                *(__nv_bfloat162*)(Chi + (size_t)r0 * DD + cc) = __nv_bfloat162(h0, h1);
                *(__nv_bfloat162*)(Clo + (size_t)r0 * DD + cc) = __nv_bfloat162(l0, l1);
                split_bf(acc[im][in][2], h0, l0);
                split_bf(acc[im][in][3], h1, l1);
                *(__nv_bfloat162*)(Chi + (size_t)(r0 + 8) * DD + cc) = __nv_bfloat162(h0, h1);
                *(__nv_bfloat162*)(Clo + (size_t)(r0 + 8) * DD + cc) = __nv_bfloat162(l0, l1);
            } else {
                float2 lo = {acc[im][in][0], acc[im][in][1]};
                float2 hi = {acc[im][in][2], acc[im][in][3]};
                *(float2*)(Cf + (size_t)r0 * DD + cc) = lo;
                *(float2*)(Cf + (size_t)(r0 + 8) * DD + cc) = hi;
            }
        }
}

#define PSTB 80
#define VSTB 272
#define AT_PHI 0
#define AT_PLO (128 * PSTB)
#define AT_VHI (2 * 128 * PSTB)
#define AT_VLO (AT_VHI + 2 * 32 * VSTB)
#define AT_MQ  (AT_VLO + 2 * 32 * VSTB)
#define AT_DEN (AT_MQ + 512)
#define AT_SMEM (AT_DEN + 512)

__global__ __launch_bounds__(256)
void k_attn(const __nv_bfloat16* __restrict__ Vhi,
            const __nv_bfloat16* __restrict__ Vlo,
            __nv_bfloat16* __restrict__ Ohi,
            __nv_bfloat16* __restrict__ Olo) {
    extern __shared__ char smem[];
    uint32_t sb = smem_to_u32(smem);
    float* mq_s = (float*)(smem + AT_MQ);
    float* den_s = (float*)(smem + AT_DEN);

    int tid = threadIdx.x;
    int wid = tid >> 5, lane = tid & 31;
    int wm = wid & 3, wn = wid >> 2;
    int bh = blockIdx.y;
    int b = bh >> 3, h = bh & 7;
    int qbase = blockIdx.x * 128;

    const float* mass = g_masses + (size_t)bh * SB;
    const float* recbase = g_recip + (size_t)qbase * SB;
    const __nv_bfloat16* vhbase = Vhi + (size_t)b * SB * DD + h * HD;
    const __nv_bfloat16* vlbase = Vlo + (size_t)b * SB * DD + h * HD;

    if (tid < 128) mq_s[tid] = mass[qbase + tid];
    __syncthreads();

    int qcls = tid >> 4, kp = tid & 15;
    float mq8[8];
#pragma unroll
    for (int i = 0; i < 8; i++) mq8[i] = mq_s[qcls * 8 + i];

    float acc[2][8][4];
#pragma unroll
    for (int im = 0; im < 2; im++)
#pragma unroll
        for (int in = 0; in < 8; in++)
#pragma unroll
            for (int q = 0; q < 4; q++) acc[im][in][q] = 0.f;
    float dpart[8];
#pragma unroll
    for (int i = 0; i < 8; i++) dpart[i] = 0.f;

    int vrow[2], vseg[2];
#pragma unroll
    for (int j = 0; j < 2; j++) {
        int i = j * 256 + tid;
        vrow[j] = i >> 4;
        vseg[j] = i & 15;
    }
    auto stage_v = [&](int kb, int buf) {
        uint32_t dh = sb + AT_VHI + buf * (32 * VSTB);
        uint32_t dl = sb + AT_VLO + buf * (32 * VSTB);
#pragma unroll
        for (int j = 0; j < 2; j++) {
            uint32_t so = (uint32_t)(vrow[j] * VSTB + vseg[j] * 16);
            size_t gs = (size_t)(kb + vrow[j]) * DD + vseg[j] * 8;
            cp16(dh + so, vhbase + gs);
            cp16(dl + so, vlbase + gs);
        }
    };

    float2 rec2[8];
    float2 mk2;
    auto load_rec = [&](int kb) {
        mk2 = *(const float2*)(mass + kb + kp * 2);
#pragma unroll
        for (int i = 0; i < 8; i++)
            rec2[i] = *(const float2*)(recbase + (size_t)(qcls * 8 + i) * SB + kb + kp * 2);
    };

    stage_v(0, 0);
    CP_COMMIT();
    load_rec(0);

    uint32_t pa_hi = sb + AT_PHI + (wm * 32 + (lane & 15)) * PSTB + (lane >> 4) * 16;
    uint32_t pa_lo = pa_hi + (AT_PLO - AT_PHI);
    uint32_t vb_off = (uint32_t)((lane & 15) * VSTB + (lane >> 4) * 16 + wn * 128);

    for (int c = 0; c < 64; c++) {
        int buf = c & 1;
#pragma unroll
        for (int i = 0; i < 8; i++) {
            float f0 = fminf(mq8[i] * mk2.x * rec2[i].x, 50.0f);
            float f1 = fminf(mq8[i] * mk2.y * rec2[i].y, 50.0f);
            float e0 = fast_exp_pos(f0);
            float e1 = fast_exp_pos(f1);
            __nv_bfloat16 h0, h1, l0, l1;
            split_bf(e0, h0, l0);
            split_bf(e1, h1, l1);
            uint32_t off = (qcls * 8 + i) * PSTB + kp * 4;
            *(uint32_t*)(smem + AT_PHI + off) = pack_bf2_u(h0, h1);
            *(uint32_t*)(smem + AT_PLO + off) = pack_bf2_u(l0, l1);
            dpart[i] += e0 + e1;
        }
        CP_WAIT(0);
        __syncthreads();

        if (c + 1 < 64) {
            stage_v((c + 1) * 32, buf ^ 1);
            CP_COMMIT();
            load_rec((c + 1) * 32);
        }

        uint32_t vh0 = sb + AT_VHI + buf * (32 * VSTB) + vb_off;
        uint32_t vl0 = sb + AT_VLO + buf * (32 * VSTB) + vb_off;
#pragma unroll
        for (int kk = 0; kk < 2; kk++) {
            uint32_t aH[2][4], aL[2][4];
#pragma unroll
            for (int im = 0; im < 2; im++) {
                ldsm_x4(aH[im], pa_hi + im * 16 * PSTB + kk * 32);
                ldsm_x4(aL[im], pa_lo + im * 16 * PSTB + kk * 32);
            }
#pragma unroll
            for (int hf = 0; hf < 2; hf++) {
                uint32_t bH[8], bL[8];
#pragma unroll
                for (int g2 = 0; g2 < 2; g2++) {
                    uint32_t nb = kk * 16 * VSTB + (hf * 2 + g2) * 32;
                    ldsm_t_x4(bH + g2 * 4, vh0 + nb);
                    ldsm_t_x4(bL + g2 * 4, vl0 + nb);
                }
#pragma unroll
                for (int im = 0; im < 2; im++)
#pragma unroll
                    for (int in4 = 0; in4 < 4; in4++) {
                        const uint32_t* ph = &bH[(in4 >> 1) * 4 + (in4 & 1) * 2];
                        const uint32_t* pl = &bL[(in4 >> 1) * 4 + (in4 & 1) * 2];
                        int in = hf * 4 + in4;
                        mma_bf16(acc[im][in], aH[im], ph);
                        mma_bf16(acc[im][in], aH[im], pl);
                        mma_bf16(acc[im][in], aL[im], ph);
                    }
            }
        }
        __syncthreads();
    }

#pragma unroll
    for (int i = 0; i < 8; i++) {
        float d = dpart[i];
        d += __shfl_xor_sync(0xffffffffu, d, 1);
        d += __shfl_xor_sync(0xffffffffu, d, 2);
        d += __shfl_xor_sync(0xffffffffu, d, 4);
        d += __shfl_xor_sync(0xffffffffu, d, 8);
        if ((lane & 15) == 0) den_s[qcls * 8 + i] = d;
    }
    __syncthreads();

    size_t orow = (size_t)b * SB + qbase;
#pragma unroll
    for (int im = 0; im < 2; im++)
#pragma unroll
        for (int in = 0; in < 8; in++) {
            int r = wm * 32 + im * 16 + (lane >> 2);
            int cc = h * HD + wn * 64 + in * 8 + 2 * (lane & 3);
            float inv0 = 1.0f / den_s[r];
            float inv1 = 1.0f / den_s[r + 8];
            __nv_bfloat16 h0, h1, l0, l1;
            split_bf(acc[im][in][0] * inv0, h0, l0);
            split_bf(acc[im][in][1] * inv0, h1, l1);
            *(__nv_bfloat162*)(Ohi + (orow + r) * DD + cc) = __nv_bfloat162(h0, h1);
            *(__nv_bfloat162*)(Olo + (orow + r) * DD + cc) = __nv_bfloat162(l0, l1);
            split_bf(acc[im][in][2] * inv1, h0, l0);
            split_bf(acc[im][in][3] * inv1, h1, l1);
            *(__nv_bfloat162*)(Ohi + (orow + r + 8) * DD + cc) = __nv_bfloat162(h0, h1);
            *(__nv_bfloat162*)(Olo + (orow + r + 8) * DD + cc) = __nv_bfloat162(l0, l1);
        }
}

extern "C" void kernel_launch(void* const* d_in, const int* in_sizes, int n_in,
                              void* d_out, int out_size) {
    const float* x      = (const float*)d_in[0];
    const float* mass_w = (const float*)d_in[1];
    const float* v_w    = (const float*)d_in[2];
    const float* out_w  = (const float*)d_in[3];
    const float* pos    = (const float*)d_in[4];
    float* out = (float*)d_out;

    cudaFuncSetAttribute(k_gemm_tc, cudaFuncAttributeMaxDynamicSharedMemorySize,
                         GT_SMEM);
    cudaFuncSetAttribute(k_attn, cudaFuncAttributeMaxDynamicSharedMemorySize,
                         AT_SMEM);

    __nv_bfloat16 *xhi, *xlo, *vhi, *vlo, *hohi, *holo, *wvhi, *wvlo, *wohi, *wolo;
    cudaGetSymbolAddress((void**)&xhi, g_xhi);
    cudaGetSymbolAddress((void**)&xlo, g_xlo);
    cudaGetSymbolAddress((void**)&vhi, g_vhi);
    cudaGetSymbolAddress((void**)&vlo, g_vlo);
    cudaGetSymbolAddress((void**)&hohi, g_hohi);
    cudaGetSymbolAddress((void**)&holo, g_holo);
    cudaGetSymbolAddress((void**)&wvhi, g_wvhi);
    cudaGetSymbolAddress((void**)&wvlo, g_wvlo);
    cudaGetSymbolAddress((void**)&wohi, g_wohi);
    cudaGetSymbolAddress((void**)&wolo, g_wolo);

    const int NX = BB * SB * DD;
    const int NW = DD * DD;

    k_recip<<<(SB * SB) / 256, 256>>>(pos);
    k_masses<<<(BB * HH * SB) / 8, 256>>>(x, mass_w);
    k_split<<<NX / 1024, 256>>>(x, xhi, xlo);
    k_split<<<NW / 1024, 256>>>(v_w, wvhi, wvlo);
    k_split<<<NW / 1024, 256>>>(out_w, wohi, wolo);
    k_gemm_tc<<<dim3(DD / 128, (BB * SB) / 128), 256, GT_SMEM>>>(
        xhi, xlo, wvhi, wvlo, nullptr, vhi, vlo);
    k_attn<<<dim3(SB / 128, BB * HH), 256, AT_SMEM>>>(vhi, vlo, hohi, holo);
    k_gemm_tc<<<dim3(DD / 128, (BB * SB) / 128), 256, GT_SMEM>>>(
        hohi, holo, wohi, wolo, out, nullptr, nullptr);
}